// round 8
// baseline (speedup 1.0000x reference)
#include <cuda_runtime.h>
#include <cuda_bf16.h>
#include <stdint.h>

// Problem constants: shape (16, 1, 320, 320) fp32, two tensors (pred, target)
#define NIMG   16
#define H      320
#define W      320
#define W2     160             // pixel-pairs per row
#define WPR    10              // 32-bit words per row (320/32)
#define NPIX   (NIMG * H * W)  // 1,638,400
#define NROWS  (NIMG * H)      // 5,120
#define SENT   0x7FFF
#define SENT2  (SENT * SENT)
#define CAPQ   0x3FFF          // saturation cap for stored squared distances
#define BIGF   1e12f
#define GRID   888             // 148 SMs * 6 blocks (co-residency via launch_bounds)
#define NTILE  (NPIX / 512)    // 3200 pair-tiles of 256 threads

// Scratch (static device globals — no allocation).
// g_D  [p]: per tensor halfword: class<<15 | exact horiz dist to opposite class
// g_Dsq[p]: per tensor halfword: class<<15 | min(dist^2, CAPQ)
__device__ __align__(256) uint32_t g_D[NPIX];
__device__ __align__(256) uint32_t g_Dsq[NPIX];
__device__ double            g_part[GRID];
__device__ unsigned          g_cnt0 = 0, g_cnt1 = 0;       // self-reset via atomicInc wrap
__device__ volatile unsigned g_sense0 = 0, g_sense1 = 0;   // flips once per launch

// ---------------------------------------------------------------------------
// Exact horizontal distance to nearest opposite-class bit; branchless 64-bit
// window covers d<=32 (overwhelmingly common), rare multi-word scan fallback.
__device__ __forceinline__ int nearest_dist64(const uint32_t* wr, int j, int L,
                                              uint32_t pol) {
    uint32_t cj   = wr[j] ^ pol;
    uint32_t cjm1 = (j > 0)       ? (wr[j - 1] ^ pol) : 0u;
    uint32_t cjp1 = (j < WPR - 1) ? (wr[j + 1] ^ pol) : 0u;

    uint64_t winL = ((uint64_t)cj << 32) | cjm1;
    int pos = 32 + L;
    uint64_t mlow = winL & ((2ull << pos) - 1ull);
    int dl;
    if (mlow) {
        dl = pos - 63 + __clzll((long long)mlow);
    } else {
        dl = SENT;
        for (int k2 = j - 2; k2 >= 0; --k2) {          // rare
            uint32_t mm = wr[k2] ^ pol;
            if (mm) { dl = j * 32 + L - (k2 * 32 + 31 - __clz(mm)); break; }
        }
    }
    uint64_t winR = ((uint64_t)cjp1 << 32) | cj;
    uint64_t mhigh = winR & (~0ull << L);
    int dr;
    if (mhigh) {
        dr = __ffsll((long long)mhigh) - 1 - L;
    } else {
        dr = SENT;
        for (int k2 = j + 2; k2 < WPR; ++k2) {         // rare
            uint32_t mm = wr[k2] ^ pol;
            if (mm) { dr = k2 * 32 + (__ffs(mm) - 1) - (j * 32 + L); break; }
        }
    }
    return min(min(dl, dr), SENT);
}

// ---------------------------------------------------------------------------
// Exact per-pixel fallback (cold; only when SIMD result may have saturated).
__device__ __noinline__ float fallback_pixel(int idx, int y) {
    uint32_t own = g_D[idx];
    uint32_t c0 = (own >> 15) & 1u;
    uint32_t c1 = (own >> 31) & 1u;
    int d;
    d = (int)(own & 0x7FFFu);         int b0 = d * d;
    d = (int)((own >> 16) & 0x7FFFu); int b1 = d * d;
    for (int dy = 1; dy < H; ++dy) {
        int dy2 = dy * dy;
        if (dy2 >= b0 && dy2 >= b1) break;
        if (y >= dy) {
            uint32_t v = g_D[idx - dy * W];
            int a0 = (((v >> 15) & 1u) == c0) ? (int)(v & 0x7FFFu) : 0;
            int a1 = (((v >> 31) & 1u) == c1) ? (int)((v >> 16) & 0x7FFFu) : 0;
            b0 = min(b0, dy2 + a0 * a0);
            b1 = min(b1, dy2 + a1 * a1);
        }
        if (y + dy < H) {
            uint32_t v = g_D[idx + dy * W];
            int a0 = (((v >> 15) & 1u) == c0) ? (int)(v & 0x7FFFu) : 0;
            int a1 = (((v >> 31) & 1u) == c1) ? (int)((v >> 16) & 0x7FFFu) : 0;
            b0 = min(b0, dy2 + a0 * a0);
            b1 = min(b1, dy2 + a1 * a1);
        }
    }
    float f0 = (b0 >= SENT2) ? (c0 ? BIGF : 0.f) : (float)b0;
    float f1 = (b1 >= SENT2) ? (c1 ? BIGF : 0.f) : (float)b1;
    return f0 + f1;
}

// ---------------------------------------------------------------------------
// One 4-dy chunk: batch all (<=8) loads first, then SIMD updates.
// All predicates are warp-uniform (y uniform per warp). dy0+3 <= 128 =>
// s16 adds cannot overflow (<= 16383 + 16384 = 32767).
__device__ __forceinline__ void chunk4(const uint2* __restrict__ DQ, int i,
                                       int y, int dy0, uint32_t mx, uint32_t my,
                                       uint32_t& bx, uint32_t& by) {
    uint2 vu[4], vd[4];
    bool pu[4], pd[4];
#pragma unroll
    for (int j = 0; j < 4; ++j) {
        int dy = dy0 + j;
        pu[j] = (y >= dy);
        pd[j] = (y + dy < H);
        if (pu[j]) vu[j] = DQ[i - dy * W2];
        if (pd[j]) vd[j] = DQ[i + dy * W2];
    }
#pragma unroll
    for (int j = 0; j < 4; ++j) {
        int dy = dy0 + j;
        uint32_t dp = (uint32_t)(dy * dy) * 0x00010001u;
        if (pu[j]) {
            bx = __vmins2(bx, __vadd2(__vmaxs2(vu[j].x ^ mx, 0u), dp));
            by = __vmins2(by, __vadd2(__vmaxs2(vu[j].y ^ my, 0u), dp));
        }
        if (pd[j]) {
            bx = __vmins2(bx, __vadd2(__vmaxs2(vd[j].x ^ mx, 0u), dp));
            by = __vmins2(by, __vadd2(__vmaxs2(vd[j].y ^ my, 0u), dp));
        }
    }
}

// ---------------------------------------------------------------------------
__global__ void __launch_bounds__(256, 6)
k_fused(const float* __restrict__ pred, const float* __restrict__ targ,
        float* __restrict__ out) {
    const int tid  = threadIdx.x;
    const int bid  = blockIdx.x;
    const int warp = tid >> 5;
    const int L    = tid & 31;

    // Read barrier senses BEFORE any work.
    const unsigned s0 = g_sense0;
    const unsigned s1 = g_sense1;

    __shared__ uint32_t srow[8][2][WPR];

    // ---------------- Phase A: horizontal pass, one warp per row ----------
    int row = bid * 8 + warp;               // 888*8 = 7104 >= 5120 rows
    if (row < NROWS) {
        int base = row * W;
        uint32_t* sp = &srow[warp][0][0];
        uint32_t* st = &srow[warp][1][0];
        for (int j = 0; j < WPR; ++j) {
            float p = pred[base + j * 32 + L];
            float t = targ[base + j * 32 + L];
            uint32_t bp = __ballot_sync(0xFFFFFFFFu, p > 0.5f);
            uint32_t bt = __ballot_sync(0xFFFFFFFFu, t > 0.5f);
            if (L == 0) { sp[j] = bp; st[j] = bt; }
        }
        __syncwarp();
        for (int j = 0; j < WPR; ++j) {
            uint32_t c0 = (sp[j] >> L) & 1u;
            uint32_t c1 = (st[j] >> L) & 1u;
            int d0 = nearest_dist64(sp, j, L, c0 ? 0xFFFFFFFFu : 0u);
            int d1 = nearest_dist64(st, j, L, c1 ? 0xFFFFFFFFu : 0u);
            int pix = base + j * 32 + L;
            g_D[pix] = (c0 << 15) | (uint32_t)d0 | (c1 << 31) | ((uint32_t)d1 << 16);
            uint32_t q0 = (c0 << 15) | (uint32_t)min(d0 * d0, CAPQ);
            uint32_t q1 = (c1 << 15) | (uint32_t)min(d1 * d1, CAPQ);
            g_Dsq[pix] = q0 | (q1 << 16);
        }
    }

    // ---------------- Grid barrier #1 (sense-reversing, self-resetting) ---
    __syncthreads();
    if (tid == 0) {
        __threadfence();
        unsigned t = atomicInc(&g_cnt0, GRID - 1);
        if (t == GRID - 1) g_sense0 = s0 ^ 1u;
        else while (g_sense0 == s0) __nanosleep(32);
        __threadfence();
    }
    __syncthreads();

    // ---------------- Phase B: SIMD vertical envelope + loss --------------
    const uint2* DQ = (const uint2*)g_Dsq;
    float fsum = 0.f;

    for (int tile = bid; tile < NTILE; tile += GRID) {
        int i = tile * 256 + tid;           // pair index (2 horiz pixels)
        int y = (i / W2) % H;               // warp-uniform (32 | 160)

        uint2 own = DQ[i];
        uint32_t mx = own.x & 0x80008000u;  // query class masks
        uint32_t my = own.y & 0x80008000u;
        uint32_t bx = __vmaxs2(own.x ^ mx, 0u);   // own sat d^2 (<= CAPQ)
        uint32_t by = __vmaxs2(own.y ^ my, 0u);

        // First chunk (dy=1..4) unconditional: P(warp exits before dy=3) ~ 2.6e-4.
        chunk4(DQ, i, y, 1, mx, my, bx, by);
        {
            uint32_t m2 = __vmaxs2(bx, by);
            int bb = max((int)(m2 >> 16), (int)(m2 & 0xFFFFu));
            // Tail chunks; dy capped at 128 (dy0<=125) => overflow-free SIMD.
            for (int dy0 = 5; dy0 <= 125 && dy0 * dy0 < bb; dy0 += 4) {
                chunk4(DQ, i, y, dy0, mx, my, bx, by);
                m2 = __vmaxs2(bx, by);
                bb = max((int)(m2 >> 16), (int)(m2 & 0xFFFFu));
            }
        }

        int b00 = (int)(bx & 0xFFFFu), b01 = (int)(bx >> 16);
        int b10 = (int)(by & 0xFFFFu), b11 = (int)(by >> 16);

        float2 pv = ((const float2*)pred)[i];
        float2 tv = ((const float2*)targ)[i];
        float e0 = pv.x - tv.x;
        float e1 = pv.y - tv.y;
        // >= CAPQ => may involve saturation or the dy cap -> exact recompute
        float f0 = (max(b00, b01) >= CAPQ) ? fallback_pixel(2 * i, y)
                                           : (float)(b00 + b01);
        float f1 = (max(b10, b11) >= CAPQ) ? fallback_pixel(2 * i + 1, y)
                                           : (float)(b10 + b11);
        fsum += e0 * e0 * f0 + e1 * e1 * f1;
    }

    // block reduce fsum -> double partial
#pragma unroll
    for (int off = 16; off; off >>= 1)
        fsum += __shfl_down_sync(0xFFFFFFFFu, fsum, off);
    __shared__ float ws[8];
    if (L == 0) ws[warp] = fsum;
    __syncthreads();
    if (tid == 0) {
        float v = ws[0];
#pragma unroll
        for (int k = 1; k < 8; ++k) v += ws[k];
        g_part[bid] = (double)v;
    }

    // ---------------- Grid barrier #2 -------------------------------------
    __syncthreads();
    if (tid == 0) {
        __threadfence();
        unsigned t = atomicInc(&g_cnt1, GRID - 1);
        if (t == GRID - 1) g_sense1 = s1 ^ 1u;
        else while (g_sense1 == s1) __nanosleep(32);
        __threadfence();
    }
    __syncthreads();

    // ---------------- Final reduction by block 0 ---------------------------
    if (bid == 0) {
        double acc = 0.0;
        for (int k = tid; k < GRID; k += 256) acc += g_part[k];
#pragma unroll
        for (int off = 16; off; off >>= 1)
            acc += __shfl_down_sync(0xFFFFFFFFu, acc, off);
        __shared__ double wd[8];
        if (L == 0) wd[warp] = acc;
        __syncthreads();
        if (tid == 0) {
            double s = wd[0];
#pragma unroll
            for (int k = 1; k < 8; ++k) s += wd[k];
            out[0] = (float)(s / (double)NPIX);
        }
    }
}

// ---------------------------------------------------------------------------
extern "C" void kernel_launch(void* const* d_in, const int* in_sizes, int n_in,
                              void* d_out, int out_size) {
    const float* pred = (const float*)d_in[0];
    const float* targ = (const float*)d_in[1];
    float* out = (float*)d_out;

    k_fused<<<GRID, 256>>>(pred, targ, out);
}

// round 9
// speedup vs baseline: 1.1044x; 1.1044x over previous
#include <cuda_runtime.h>
#include <cuda_bf16.h>
#include <stdint.h>

// Problem constants: shape (16, 1, 320, 320) fp32, two tensors (pred, target)
#define NIMG   16
#define H      320
#define W      320
#define W2     160             // pixel-pairs per row
#define WPR    10              // 32-bit words per row (320/32)
#define NPIX   (NIMG * H * W)  // 1,638,400
#define NROWS  (NIMG * H)      // 5,120
#define SENT   0x7FFF
#define SENT2  (SENT * SENT)
#define CAPQ   0x3FFF          // saturation cap for stored squared distances
#define BIGF   1e12f
#define SW     8               // strip width in pairs (16 pixels)
#define NSTRIP (W2 / SW)       // 20 strips per image
#define GRID   (NIMG * NSTRIP) // 320 blocks (all co-resident: 21KB smem, regs<=48)
#define TPAIRS (H * SW)        // 2560 pairs per strip tile

// Scratch (static device globals — no allocation).
// g_D  [p]: per tensor halfword: class<<15 | exact horiz dist to opposite class
// g_Dsq[p]: per tensor halfword: class<<15 | min(dist^2, CAPQ)
__device__ __align__(256) uint32_t g_D[NPIX];
__device__ __align__(256) uint32_t g_Dsq[NPIX];
__device__ double            g_part[GRID];
__device__ unsigned          g_cnt0 = 0, g_cnt1 = 0;       // self-reset via atomicInc wrap
__device__ volatile unsigned g_sense0 = 0, g_sense1 = 0;   // flips once per launch

// ---------------------------------------------------------------------------
// Exact horizontal distance to nearest opposite-class bit; branchless 64-bit
// window covers d<=32 (overwhelmingly common), rare multi-word scan fallback.
__device__ __forceinline__ int nearest_dist64(const uint32_t* wr, int j, int L,
                                              uint32_t pol) {
    uint32_t cj   = wr[j] ^ pol;
    uint32_t cjm1 = (j > 0)       ? (wr[j - 1] ^ pol) : 0u;
    uint32_t cjp1 = (j < WPR - 1) ? (wr[j + 1] ^ pol) : 0u;

    uint64_t winL = ((uint64_t)cj << 32) | cjm1;
    int pos = 32 + L;
    uint64_t mlow = winL & ((2ull << pos) - 1ull);
    int dl;
    if (mlow) {
        dl = pos - 63 + __clzll((long long)mlow);
    } else {
        dl = SENT;
        for (int k2 = j - 2; k2 >= 0; --k2) {          // rare
            uint32_t mm = wr[k2] ^ pol;
            if (mm) { dl = j * 32 + L - (k2 * 32 + 31 - __clz(mm)); break; }
        }
    }
    uint64_t winR = ((uint64_t)cjp1 << 32) | cj;
    uint64_t mhigh = winR & (~0ull << L);
    int dr;
    if (mhigh) {
        dr = __ffsll((long long)mhigh) - 1 - L;
    } else {
        dr = SENT;
        for (int k2 = j + 2; k2 < WPR; ++k2) {         // rare
            uint32_t mm = wr[k2] ^ pol;
            if (mm) { dr = k2 * 32 + (__ffs(mm) - 1) - (j * 32 + L); break; }
        }
    }
    return min(min(dl, dr), SENT);
}

// ---------------------------------------------------------------------------
// Exact per-pixel fallback (cold; only when SIMD result may have saturated).
__device__ __noinline__ float fallback_pixel(int idx, int y) {
    uint32_t own = g_D[idx];
    uint32_t c0 = (own >> 15) & 1u;
    uint32_t c1 = (own >> 31) & 1u;
    int d;
    d = (int)(own & 0x7FFFu);         int b0 = d * d;
    d = (int)((own >> 16) & 0x7FFFu); int b1 = d * d;
    for (int dy = 1; dy < H; ++dy) {
        int dy2 = dy * dy;
        if (dy2 >= b0 && dy2 >= b1) break;
        if (y >= dy) {
            uint32_t v = g_D[idx - dy * W];
            int a0 = (((v >> 15) & 1u) == c0) ? (int)(v & 0x7FFFu) : 0;
            int a1 = (((v >> 31) & 1u) == c1) ? (int)((v >> 16) & 0x7FFFu) : 0;
            b0 = min(b0, dy2 + a0 * a0);
            b1 = min(b1, dy2 + a1 * a1);
        }
        if (y + dy < H) {
            uint32_t v = g_D[idx + dy * W];
            int a0 = (((v >> 15) & 1u) == c0) ? (int)(v & 0x7FFFu) : 0;
            int a1 = (((v >> 31) & 1u) == c1) ? (int)((v >> 16) & 0x7FFFu) : 0;
            b0 = min(b0, dy2 + a0 * a0);
            b1 = min(b1, dy2 + a1 * a1);
        }
    }
    float f0 = (b0 >= SENT2) ? (c0 ? BIGF : 0.f) : (float)b0;
    float f1 = (b1 >= SENT2) ? (c1 ? BIGF : 0.f) : (float)b1;
    return f0 + f1;
}

// ---------------------------------------------------------------------------
__global__ void __launch_bounds__(256)
k_fused(const float* __restrict__ pred, const float* __restrict__ targ,
        float* __restrict__ out) {
    const int tid  = threadIdx.x;
    const int bid  = blockIdx.x;
    const int warp = tid >> 5;
    const int L    = tid & 31;

    // Read barrier senses BEFORE any work.
    const unsigned s0 = g_sense0;
    const unsigned s1 = g_sense1;

    // Phase B column-strip tile (20KB). Phase A aliases its head (640B) for
    // row bit-words — safe: grid barrier separates the phases.
    __shared__ uint2 tile[TPAIRS];
    uint32_t (*srow)[2][WPR] = (uint32_t(*)[2][WPR])tile;

    // ---------------- Phase A: horizontal pass, one warp per row ----------
#pragma unroll
    for (int t = 0; t < 2; ++t) {
        int row = bid * 8 + warp + t * (GRID * 8);   // 2*2560 = 5120 rows exact
        int base = row * W;
        uint32_t* sp = &srow[warp][0][0];
        uint32_t* st = &srow[warp][1][0];
        for (int j = 0; j < WPR; ++j) {
            float p = pred[base + j * 32 + L];
            float tt = targ[base + j * 32 + L];
            uint32_t bp = __ballot_sync(0xFFFFFFFFu, p > 0.5f);
            uint32_t bt = __ballot_sync(0xFFFFFFFFu, tt > 0.5f);
            if (L == 0) { sp[j] = bp; st[j] = bt; }
        }
        __syncwarp();
        for (int j = 0; j < WPR; ++j) {
            uint32_t c0 = (sp[j] >> L) & 1u;
            uint32_t c1 = (st[j] >> L) & 1u;
            int d0 = nearest_dist64(sp, j, L, c0 ? 0xFFFFFFFFu : 0u);
            int d1 = nearest_dist64(st, j, L, c1 ? 0xFFFFFFFFu : 0u);
            int pix = base + j * 32 + L;
            g_D[pix] = (c0 << 15) | (uint32_t)d0 | (c1 << 31) | ((uint32_t)d1 << 16);
            uint32_t q0 = (c0 << 15) | (uint32_t)min(d0 * d0, CAPQ);
            uint32_t q1 = (c1 << 15) | (uint32_t)min(d1 * d1, CAPQ);
            g_Dsq[pix] = q0 | (q1 << 16);
        }
        __syncwarp();
    }

    // ---------------- Grid barrier #1 (sense-reversing, self-resetting) ---
    __syncthreads();
    if (tid == 0) {
        __threadfence();
        unsigned t = atomicInc(&g_cnt0, GRID - 1);
        if (t == GRID - 1) g_sense0 = s0 ^ 1u;
        else while (g_sense0 == s0) __nanosleep(32);
        __threadfence();
    }
    __syncthreads();

    // ---------------- Phase B: smem column-strip vertical pass + loss ------
    const int img   = bid / NSTRIP;
    const int strip = bid - img * NSTRIP;
    const uint2* DQ = (const uint2*)g_Dsq;
    // pair index of tile element (y,px): gbase + y*W2 + px
    const int gbase = img * H * W2 + strip * SW;

    // stage the strip: fully coalesced, one read per pixel
    for (int idx = tid; idx < TPAIRS; idx += 256) {
        int y = idx >> 3, px = idx & 7;
        tile[idx] = DQ[gbase + y * W2 + px];
    }
    __syncthreads();

    float fsum = 0.f;
#pragma unroll
    for (int k = 0; k < TPAIRS / 256; ++k) {         // 10 pairs per thread
        int idx = k * 256 + tid;
        int y = idx >> 3;

        uint2 own = tile[idx];
        uint32_t mx = own.x & 0x80008000u;           // query class masks
        uint32_t my = own.y & 0x80008000u;
        uint32_t bx = __vmaxs2(own.x ^ mx, 0u);      // own sat d^2 (<= CAPQ)
        uint32_t by = __vmaxs2(own.y ^ my, 0u);

        // dy loop entirely in smem; dy capped at 128 => s16 adds can't overflow
        int bb;
        {
            uint32_t m2 = __vmaxs2(bx, by);
            bb = max((int)(m2 >> 16), (int)(m2 & 0xFFFFu));
        }
        for (int dy = 1; dy <= 128 && dy * dy < bb; ++dy) {
            uint32_t dp = (uint32_t)(dy * dy) * 0x00010001u;
            if (y >= dy) {
                uint2 v = tile[idx - dy * SW];
                bx = __vmins2(bx, __vadd2(__vmaxs2(v.x ^ mx, 0u), dp));
                by = __vmins2(by, __vadd2(__vmaxs2(v.y ^ my, 0u), dp));
            }
            if (y + dy < H) {
                uint2 v = tile[idx + dy * SW];
                bx = __vmins2(bx, __vadd2(__vmaxs2(v.x ^ mx, 0u), dp));
                by = __vmins2(by, __vadd2(__vmaxs2(v.y ^ my, 0u), dp));
            }
            uint32_t m2 = __vmaxs2(bx, by);
            bb = max((int)(m2 >> 16), (int)(m2 & 0xFFFFu));
        }

        int b00 = (int)(bx & 0xFFFFu), b01 = (int)(bx >> 16);
        int b10 = (int)(by & 0xFFFFu), b11 = (int)(by >> 16);

        int gp = gbase + y * W2 + (idx & 7);         // global pair index
        float2 pv = ((const float2*)pred)[gp];
        float2 tv = ((const float2*)targ)[gp];
        float e0 = pv.x - tv.x;
        float e1 = pv.y - tv.y;
        // >= CAPQ => may involve saturation or the dy cap -> exact recompute
        float f0 = (max(b00, b01) >= CAPQ) ? fallback_pixel(2 * gp, y)
                                           : (float)(b00 + b01);
        float f1 = (max(b10, b11) >= CAPQ) ? fallback_pixel(2 * gp + 1, y)
                                           : (float)(b10 + b11);
        fsum += e0 * e0 * f0 + e1 * e1 * f1;
    }

    // block reduce fsum -> double partial
#pragma unroll
    for (int off = 16; off; off >>= 1)
        fsum += __shfl_down_sync(0xFFFFFFFFu, fsum, off);
    __shared__ float ws[8];
    if (L == 0) ws[warp] = fsum;
    __syncthreads();
    if (tid == 0) {
        float v = ws[0];
#pragma unroll
        for (int k = 1; k < 8; ++k) v += ws[k];
        g_part[bid] = (double)v;
    }

    // ---------------- Grid barrier #2 -------------------------------------
    __syncthreads();
    if (tid == 0) {
        __threadfence();
        unsigned t = atomicInc(&g_cnt1, GRID - 1);
        if (t == GRID - 1) g_sense1 = s1 ^ 1u;
        else while (g_sense1 == s1) __nanosleep(32);
        __threadfence();
    }
    __syncthreads();

    // ---------------- Final reduction by block 0 ---------------------------
    if (bid == 0) {
        double acc = 0.0;
        for (int k = tid; k < GRID; k += 256) acc += g_part[k];
#pragma unroll
        for (int off = 16; off; off >>= 1)
            acc += __shfl_down_sync(0xFFFFFFFFu, acc, off);
        __shared__ double wd[8];
        if (L == 0) wd[warp] = acc;
        __syncthreads();
        if (tid == 0) {
            double s = wd[0];
#pragma unroll
            for (int k = 1; k < 8; ++k) s += wd[k];
            out[0] = (float)(s / (double)NPIX);
        }
    }
}

// ---------------------------------------------------------------------------
extern "C" void kernel_launch(void* const* d_in, const int* in_sizes, int n_in,
                              void* d_out, int out_size) {
    const float* pred = (const float*)d_in[0];
    const float* targ = (const float*)d_in[1];
    float* out = (float*)d_out;

    k_fused<<<GRID, 256>>>(pred, targ, out);
}

// round 11
// speedup vs baseline: 1.2961x; 1.1736x over previous
#include <cuda_runtime.h>
#include <cuda_bf16.h>
#include <stdint.h>

// Problem constants: shape (16, 1, 320, 320) fp32, two tensors (pred, target)
#define NIMG   16
#define H      320
#define W      320
#define W2     160             // pixel-pairs per row
#define WPR    10              // 32-bit words per row (320/32)
#define NPIX   (NIMG * H * W)  // 1,638,400
#define NROWS  (NIMG * H)      // 5,120
#define SENT   0x7FFF
#define SENT2  (SENT * SENT)
#define CAPQ   0x3FFF          // saturation cap for stored squared distances
#define BIGF   1e12f
#define SW     4               // strip width in pairs (8 pixels)
#define NSTRIP (W2 / SW)       // 40 strips per image
#define GRID   (NIMG * NSTRIP) // 640 blocks; co-residency: 5 blk/SM max (51KB smem)
#define TPAIRS (H * SW)        // 1280 pairs per strip tile

// Scratch (static device globals — no allocation).
// g_D  [p]: per tensor halfword: class<<15 | exact horiz dist to opposite class
// g_Dsq[p]: per tensor halfword: class<<15 | min(dist^2, CAPQ)
__device__ __align__(256) uint32_t g_D[NPIX];
__device__ __align__(256) uint32_t g_Dsq[NPIX];
__device__ double            g_part[GRID];
__device__ unsigned          g_cnt0 = 0, g_cnt1 = 0;       // self-reset via atomicInc wrap
__device__ volatile unsigned g_sense0 = 0, g_sense1 = 0;   // flips once per launch

// ---------------------------------------------------------------------------
// Exact horizontal distance to nearest opposite-class bit; branchless 64-bit
// window covers d<=32 (overwhelmingly common), rare multi-word scan fallback.
__device__ __forceinline__ int nearest_dist64(const uint32_t* wr, int j, int L,
                                              uint32_t pol) {
    uint32_t cj   = wr[j] ^ pol;
    uint32_t cjm1 = (j > 0)       ? (wr[j - 1] ^ pol) : 0u;
    uint32_t cjp1 = (j < WPR - 1) ? (wr[j + 1] ^ pol) : 0u;

    uint64_t winL = ((uint64_t)cj << 32) | cjm1;
    int pos = 32 + L;
    uint64_t mlow = winL & ((2ull << pos) - 1ull);
    int dl;
    if (mlow) {
        dl = pos - 63 + __clzll((long long)mlow);
    } else {
        dl = SENT;
        for (int k2 = j - 2; k2 >= 0; --k2) {          // rare
            uint32_t mm = wr[k2] ^ pol;
            if (mm) { dl = j * 32 + L - (k2 * 32 + 31 - __clz(mm)); break; }
        }
    }
    uint64_t winR = ((uint64_t)cjp1 << 32) | cj;
    uint64_t mhigh = winR & (~0ull << L);
    int dr;
    if (mhigh) {
        dr = __ffsll((long long)mhigh) - 1 - L;
    } else {
        dr = SENT;
        for (int k2 = j + 2; k2 < WPR; ++k2) {         // rare
            uint32_t mm = wr[k2] ^ pol;
            if (mm) { dr = k2 * 32 + (__ffs(mm) - 1) - (j * 32 + L); break; }
        }
    }
    return min(min(dl, dr), SENT);
}

// ---------------------------------------------------------------------------
// Exact per-pixel fallback (cold; only when SIMD result may have saturated).
__device__ __noinline__ float fallback_pixel(int idx, int y) {
    uint32_t own = g_D[idx];
    uint32_t c0 = (own >> 15) & 1u;
    uint32_t c1 = (own >> 31) & 1u;
    int d;
    d = (int)(own & 0x7FFFu);         int b0 = d * d;
    d = (int)((own >> 16) & 0x7FFFu); int b1 = d * d;
    for (int dy = 1; dy < H; ++dy) {
        int dy2 = dy * dy;
        if (dy2 >= b0 && dy2 >= b1) break;
        if (y >= dy) {
            uint32_t v = g_D[idx - dy * W];
            int a0 = (((v >> 15) & 1u) == c0) ? (int)(v & 0x7FFFu) : 0;
            int a1 = (((v >> 31) & 1u) == c1) ? (int)((v >> 16) & 0x7FFFu) : 0;
            b0 = min(b0, dy2 + a0 * a0);
            b1 = min(b1, dy2 + a1 * a1);
        }
        if (y + dy < H) {
            uint32_t v = g_D[idx + dy * W];
            int a0 = (((v >> 15) & 1u) == c0) ? (int)(v & 0x7FFFu) : 0;
            int a1 = (((v >> 31) & 1u) == c1) ? (int)((v >> 16) & 0x7FFFu) : 0;
            b0 = min(b0, dy2 + a0 * a0);
            b1 = min(b1, dy2 + a1 * a1);
        }
    }
    float f0 = (b0 >= SENT2) ? (c0 ? BIGF : 0.f) : (float)b0;
    float f1 = (b1 >= SENT2) ? (c1 ? BIGF : 0.f) : (float)b1;
    return f0 + f1;
}

// ---------------------------------------------------------------------------
__global__ void __launch_bounds__(256, 5)
k_fused(const float* __restrict__ pred, const float* __restrict__ targ,
        float* __restrict__ out) {
    const int tid  = threadIdx.x;
    const int bid  = blockIdx.x;
    const int warp = tid >> 5;
    const int L    = tid & 31;

    // Read barrier senses BEFORE any work.
    const unsigned s0 = g_sense0;
    const unsigned s1 = g_sense1;

    // Phase B column-strip tile (10.25KB). Phase A aliases its head (640B)
    // for row bit-words — safe: grid barrier separates the phases.
    __shared__ uint2 tile[TPAIRS];
    uint32_t (*srow)[2][WPR] = (uint32_t(*)[2][WPR])tile;

    // ---------------- Phase A: horizontal pass, ONE row per warp ----------
    {
        int row = bid * 8 + warp;            // 640*8 = 5120 rows exact
        int base = row * W;
        uint32_t* sp = &srow[warp][0][0];
        uint32_t* st = &srow[warp][1][0];
        for (int j = 0; j < WPR; ++j) {
            float p  = pred[base + j * 32 + L];
            float tt = targ[base + j * 32 + L];
            uint32_t bp = __ballot_sync(0xFFFFFFFFu, p > 0.5f);
            uint32_t bt = __ballot_sync(0xFFFFFFFFu, tt > 0.5f);
            if (L == 0) { sp[j] = bp; st[j] = bt; }
        }
        __syncwarp();
        for (int j = 0; j < WPR; ++j) {
            uint32_t c0 = (sp[j] >> L) & 1u;
            uint32_t c1 = (st[j] >> L) & 1u;
            int d0 = nearest_dist64(sp, j, L, c0 ? 0xFFFFFFFFu : 0u);
            int d1 = nearest_dist64(st, j, L, c1 ? 0xFFFFFFFFu : 0u);
            int pix = base + j * 32 + L;
            g_D[pix] = (c0 << 15) | (uint32_t)d0 | (c1 << 31) | ((uint32_t)d1 << 16);
            uint32_t q0 = (c0 << 15) | (uint32_t)min(d0 * d0, CAPQ);
            uint32_t q1 = (c1 << 15) | (uint32_t)min(d1 * d1, CAPQ);
            g_Dsq[pix] = q0 | (q1 << 16);
        }
    }

    // ---------------- Grid barrier #1 (sense-reversing, self-resetting) ---
    __syncthreads();
    if (tid == 0) {
        __threadfence();
        unsigned t = atomicInc(&g_cnt0, GRID - 1);
        if (t == GRID - 1) g_sense0 = s0 ^ 1u;
        else while (g_sense0 == s0) __nanosleep(32);
        __threadfence();
    }
    __syncthreads();

    // ---------------- Phase B: smem column-strip vertical pass + loss ------
    const int img   = bid / NSTRIP;
    const int strip = bid - img * NSTRIP;
    const uint2* DQ = (const uint2*)g_Dsq;
    // pair index of tile element (y,px): gbase + y*W2 + px
    const int gbase = img * H * W2 + strip * SW;

    // stage the strip: fully coalesced, one read per pixel
    for (int idx = tid; idx < TPAIRS; idx += 256) {
        int y = idx >> 2, px = idx & 3;
        tile[idx] = DQ[gbase + y * W2 + px];
    }
    __syncthreads();

    float fsum = 0.f;
#pragma unroll
    for (int k = 0; k < TPAIRS / 256; ++k) {         // 5 pairs per thread
        int idx = k * 256 + tid;
        int y = idx >> 2;

        uint2 own = tile[idx];
        uint32_t mx = own.x & 0x80008000u;           // query class masks
        uint32_t my = own.y & 0x80008000u;
        uint32_t bx = __vmaxs2(own.x ^ mx, 0u);      // own sat d^2 (<= CAPQ)
        uint32_t by = __vmaxs2(own.y ^ my, 0u);

        // dy loop entirely in smem, 2 dys per exit check; dy capped at 128
        // (chunk start <=127) => s16 adds can't overflow (16383+16384=32767).
        int bb;
        {
            uint32_t m2 = __vmaxs2(bx, by);
            bb = max((int)(m2 >> 16), (int)(m2 & 0xFFFFu));
        }
        for (int dy = 1; dy <= 127 && dy * dy < bb; dy += 2) {
            int dya = dy, dyb = dy + 1;
            uint32_t dpa = (uint32_t)(dya * dya) * 0x00010001u;
            uint32_t dpb = (uint32_t)(dyb * dyb) * 0x00010001u;
            bool ua = (y >= dya), ub = (y >= dyb);
            bool da = (y + dya < H), db = (y + dyb < H);
            uint2 vua, vub, vda, vdb;
            if (ua) vua = tile[idx - dya * SW];
            if (da) vda = tile[idx + dya * SW];
            if (ub) vub = tile[idx - dyb * SW];
            if (db) vdb = tile[idx + dyb * SW];
            if (ua) {
                bx = __vmins2(bx, __vadd2(__vmaxs2(vua.x ^ mx, 0u), dpa));
                by = __vmins2(by, __vadd2(__vmaxs2(vua.y ^ my, 0u), dpa));
            }
            if (da) {
                bx = __vmins2(bx, __vadd2(__vmaxs2(vda.x ^ mx, 0u), dpa));
                by = __vmins2(by, __vadd2(__vmaxs2(vda.y ^ my, 0u), dpa));
            }
            if (ub) {
                bx = __vmins2(bx, __vadd2(__vmaxs2(vub.x ^ mx, 0u), dpb));
                by = __vmins2(by, __vadd2(__vmaxs2(vub.y ^ my, 0u), dpb));
            }
            if (db) {
                bx = __vmins2(bx, __vadd2(__vmaxs2(vdb.x ^ mx, 0u), dpb));
                by = __vmins2(by, __vadd2(__vmaxs2(vdb.y ^ my, 0u), dpb));
            }
            uint32_t m2 = __vmaxs2(bx, by);
            bb = max((int)(m2 >> 16), (int)(m2 & 0xFFFFu));
        }

        int b00 = (int)(bx & 0xFFFFu), b01 = (int)(bx >> 16);
        int b10 = (int)(by & 0xFFFFu), b11 = (int)(by >> 16);

        int gp = gbase + y * W2 + (idx & 3);         // global pair index
        float2 pv = ((const float2*)pred)[gp];
        float2 tv = ((const float2*)targ)[gp];
        float e0 = pv.x - tv.x;
        float e1 = pv.y - tv.y;
        // >= CAPQ => may involve saturation or the dy cap -> exact recompute
        float f0 = (max(b00, b01) >= CAPQ) ? fallback_pixel(2 * gp, y)
                                           : (float)(b00 + b01);
        float f1 = (max(b10, b11) >= CAPQ) ? fallback_pixel(2 * gp + 1, y)
                                           : (float)(b10 + b11);
        fsum += e0 * e0 * f0 + e1 * e1 * f1;
    }

    // block reduce fsum -> double partial
#pragma unroll
    for (int off = 16; off; off >>= 1)
        fsum += __shfl_down_sync(0xFFFFFFFFu, fsum, off);
    __shared__ float ws[8];
    if (L == 0) ws[warp] = fsum;
    __syncthreads();
    if (tid == 0) {
        float v = ws[0];
#pragma unroll
        for (int k = 1; k < 8; ++k) v += ws[k];
        g_part[bid] = (double)v;
    }

    // ---------------- Grid barrier #2 -------------------------------------
    __syncthreads();
    if (tid == 0) {
        __threadfence();
        unsigned t = atomicInc(&g_cnt1, GRID - 1);
        if (t == GRID - 1) g_sense1 = s1 ^ 1u;
        else while (g_sense1 == s1) __nanosleep(32);
        __threadfence();
    }
    __syncthreads();

    // ---------------- Final reduction by block 0 ---------------------------
    if (bid == 0) {
        double acc = 0.0;
        for (int k = tid; k < GRID; k += 256) acc += g_part[k];
#pragma unroll
        for (int off = 16; off; off >>= 1)
            acc += __shfl_down_sync(0xFFFFFFFFu, acc, off);
        __shared__ double wd[8];
        if (L == 0) wd[warp] = acc;
        __syncthreads();
        if (tid == 0) {
            double s = wd[0];
#pragma unroll
            for (int k = 1; k < 8; ++k) s += wd[k];
            out[0] = (float)(s / (double)NPIX);
        }
    }
}

// ---------------------------------------------------------------------------
extern "C" void kernel_launch(void* const* d_in, const int* in_sizes, int n_in,
                              void* d_out, int out_size) {
    const float* pred = (const float*)d_in[0];
    const float* targ = (const float*)d_in[1];
    float* out = (float*)d_out;

    k_fused<<<GRID, 256>>>(pred, targ, out);
}